// round 6
// baseline (speedup 1.0000x reference)
#include <cuda_runtime.h>
#include <cuda_bf16.h>
#include <cstdint>

// out[b] = ||x_b||^2 * (x_b^T rho x_b)
// Z = X @ rho^T via mma.sync m16n8k16 bf16. Split: Z = Xh*Rh + Xh*Rl + Xl*Rh.
// R6: warp tiling 2(M)x8(N), ldsm.x4 B loads, register-pipelined fragments.

#define BATCH 4096
#define DIMX 256
#define TILE_M 32
#define NTHREADS 512
#define NKCHUNKS 4          // K chunks of 64

__device__ __nv_bfloat16 g_Rh[DIMX * DIMX];
__device__ __nv_bfloat16 g_Rl[DIMX * DIMX];

// ---- dynamic smem layout (bytes) ----
#define A_STRIDE 264        // bf16 elems/row (528B pitch; 528%128=16 -> conflict-free ldsm)
#define B_STRIDE 72         // bf16 elems/row (144B pitch; 144%128=16 -> conflict-free)
#define SM_AH    0                       // 32 x 264 x2B = 16896
#define SM_AL    16896
#define SM_BH0   33792                   // 256 x 72 x2B = 36864
#define SM_BL0   70656
#define SM_BH1   107520
#define SM_BL1   144384
#define SM_QP    181248                  // float[16][16] = 1024
#define SM_NP    182272                  // float[16][16] = 1024
#define SMEM_TOTAL 183296

__device__ __forceinline__ uint32_t smem_u32(const void* p) {
    uint32_t a;
    asm("{ .reg .u64 t; cvta.to.shared.u64 t, %1; cvt.u32.u64 %0, t; }"
        : "=r"(a) : "l"(p));
    return a;
}
__device__ __forceinline__ void cp16(uint32_t dst, const void* src) {
    asm volatile("cp.async.cg.shared.global [%0], [%1], 16;" :: "r"(dst), "l"(src));
}
__device__ __forceinline__ void cp_commit() {
    asm volatile("cp.async.commit_group;" ::: "memory");
}
__device__ __forceinline__ void mma16816(float* c, const uint32_t* a, const uint32_t* b) {
    asm volatile(
        "mma.sync.aligned.m16n8k16.row.col.f32.bf16.bf16.f32 "
        "{%0,%1,%2,%3}, {%4,%5,%6,%7}, {%8,%9}, {%0,%1,%2,%3};"
        : "+f"(c[0]), "+f"(c[1]), "+f"(c[2]), "+f"(c[3])
        : "r"(a[0]), "r"(a[1]), "r"(a[2]), "r"(a[3]), "r"(b[0]), "r"(b[1]));
}
__device__ __forceinline__ void ldsm_x4(uint32_t* r, uint32_t addr) {
    asm volatile("ldmatrix.sync.aligned.m8n8.x4.shared.b16 {%0,%1,%2,%3}, [%4];"
                 : "=r"(r[0]), "=r"(r[1]), "=r"(r[2]), "=r"(r[3]) : "r"(addr));
}
__device__ __forceinline__ void split4(const float4 v, uint2& hi, uint2& lo) {
    __nv_bfloat162 h01 = __float22bfloat162_rn(make_float2(v.x, v.y));
    __nv_bfloat162 h23 = __float22bfloat162_rn(make_float2(v.z, v.w));
    float2 f01 = __bfloat1622float2(h01);
    float2 f23 = __bfloat1622float2(h23);
    __nv_bfloat162 l01 = __float22bfloat162_rn(make_float2(v.x - f01.x, v.y - f01.y));
    __nv_bfloat162 l23 = __float22bfloat162_rn(make_float2(v.z - f23.x, v.w - f23.y));
    hi.x = *reinterpret_cast<const uint32_t*>(&h01);
    hi.y = *reinterpret_cast<const uint32_t*>(&h23);
    lo.x = *reinterpret_cast<const uint32_t*>(&l01);
    lo.y = *reinterpret_cast<const uint32_t*>(&l23);
}

__global__ void cvt_rho(const float* __restrict__ R) {
    const int NR = DIMX * DIMX / 4;
    int i = blockIdx.x * blockDim.x + threadIdx.x;
    if (i >= NR) return;
    float4 v = reinterpret_cast<const float4*>(R)[i];
    uint2 hi, lo;
    split4(v, hi, lo);
    reinterpret_cast<uint2*>(g_Rh)[i] = hi;
    reinterpret_cast<uint2*>(g_Rl)[i] = lo;
}

__global__ __launch_bounds__(NTHREADS, 1)
void qmd_mma(const float* __restrict__ X, float* __restrict__ out) {
    extern __shared__ char smem[];
    const uint32_t sb = smem_u32(smem);
    const int t = threadIdx.x;
    const int wid = t >> 5;
    const int lane = t & 31;
    const int b0 = blockIdx.x * TILE_M;

    const int mg = wid >> 3;        // 0..1 : M half (16 rows)
    const int ng = wid & 7;         // 0..7 : N slice (32 cols)
    const int n_base = ng * 32;

    // ---- prefetch B chunks 0,1 via cp.async (double buffer) ----
    #pragma unroll
    for (int kb = 0; kb < 2; kb++) {
        const uint32_t bh = kb ? SM_BH1 : SM_BH0;
        const uint32_t bl = kb ? SM_BL1 : SM_BL0;
        #pragma unroll
        for (int i = 0; i < 8; i++) {
            const int f = t + i * NTHREADS;         // 0..4095
            const int arr = f >> 11, rem = f & 2047;
            const int n = rem >> 3, c = rem & 7;
            const uint32_t dst = sb + (arr ? bl : bh) + n * (B_STRIDE * 2) + c * 16;
            const __nv_bfloat16* src = (arr ? g_Rl : g_Rh) + (size_t)n * DIMX + kb * 64 + c * 8;
            cp16(dst, src);
        }
        cp_commit();
    }

    // ---- load + convert A tile (overlaps cp.async) ----
    {
        const float4* __restrict__ Xg = reinterpret_cast<const float4*>(X);
        #pragma unroll
        for (int i = 0; i < 4; i++) {
            const int f = t + i * NTHREADS;         // 0..2047
            const int r = f >> 6, c4 = f & 63;
            float4 v = Xg[(size_t)(b0 + r) * (DIMX / 4) + c4];
            uint2 hi, lo;
            split4(v, hi, lo);
            const uint32_t off = r * (A_STRIDE * 2) + c4 * 8;
            *reinterpret_cast<uint2*>(smem + SM_AH + off) = hi;
            *reinterpret_cast<uint2*>(smem + SM_AL + off) = lo;
        }
    }

    // ---- precomputed ldmatrix base addresses (k-local offset added per step) ----
    const int m_idx = lane >> 3;    // 0..3
    // A (m16 x k16, x4): grp0 m0-7@k0, grp1 m8-15@k0, grp2 m0-7@k8, grp3 m8-15@k8
    const uint32_t a_row = mg * 16 + (m_idx & 1) * 8 + (lane & 7);
    const uint32_t a_base = a_row * (A_STRIDE * 2) + (m_idx >> 1) * 16;
    // B (n16 x k16, x4): grp0 n0-7@k0, grp1 n0-7@k8, grp2 n8-15@k0, grp3 n8-15@k8
    const uint32_t b_rowpart = (m_idx >> 1) * 8 + (lane & 7);
    // two x4 loads per array: n_base+0 and n_base+16
    const uint32_t b_base0 = (n_base + b_rowpart) * (B_STRIDE * 2) + (m_idx & 1) * 16;
    const uint32_t b_base1 = (n_base + 16 + b_rowpart) * (B_STRIDE * 2) + (m_idx & 1) * 16;

    float acc[4][4];
    #pragma unroll
    for (int ni = 0; ni < 4; ni++)
        #pragma unroll
        for (int e = 0; e < 4; e++) acc[ni][e] = 0.0f;

    // fragment double buffers
    uint32_t aH[2][4], aL[2][4], bH[2][8], bL[2][8];

    for (int kb = 0; kb < NKCHUNKS; kb++) {
        if (kb == NKCHUNKS - 1)
            asm volatile("cp.async.wait_group 0;" ::: "memory");
        else
            asm volatile("cp.async.wait_group 1;" ::: "memory");
        __syncthreads();

        const uint32_t bh = sb + ((kb & 1) ? SM_BH1 : SM_BH0);
        const uint32_t bl = sb + ((kb & 1) ? SM_BL1 : SM_BL0);
        const uint32_t ah = sb + SM_AH + a_base + (kb * 64) * 2;
        const uint32_t al = sb + SM_AL + a_base + (kb * 64) * 2;

        // prime stage 0 (k16 = 0)
        ldsm_x4(aH[0], ah);
        ldsm_x4(aL[0], al);
        ldsm_x4(&bH[0][0], bh + b_base0);
        ldsm_x4(&bH[0][4], bh + b_base1);
        ldsm_x4(&bL[0][0], bl + b_base0);
        ldsm_x4(&bL[0][4], bl + b_base1);

        #pragma unroll
        for (int k16 = 0; k16 < 4; k16++) {
            const int cur = k16 & 1, nxt = cur ^ 1;
            if (k16 < 3) {
                const uint32_t ko = (k16 + 1) * 32;   // 16 cols * 2B
                ldsm_x4(aH[nxt], ah + ko);
                ldsm_x4(aL[nxt], al + ko);
                ldsm_x4(&bH[nxt][0], bh + b_base0 + ko);
                ldsm_x4(&bH[nxt][4], bh + b_base1 + ko);
                ldsm_x4(&bL[nxt][0], bl + b_base0 + ko);
                ldsm_x4(&bL[nxt][4], bl + b_base1 + ko);
            }
            #pragma unroll
            for (int ni = 0; ni < 4; ni++) {
                mma16816(acc[ni], aH[cur], &bH[cur][ni * 2]);
                mma16816(acc[ni], aH[cur], &bL[cur][ni * 2]);
                mma16816(acc[ni], aL[cur], &bH[cur][ni * 2]);
            }
        }
        __syncthreads();

        if (kb < NKCHUNKS - 2) {
            const int nk = kb + 2;
            const uint32_t dbh = (kb & 1) ? SM_BH1 : SM_BH0;
            const uint32_t dbl = (kb & 1) ? SM_BL1 : SM_BL0;
            #pragma unroll
            for (int i = 0; i < 8; i++) {
                const int f = t + i * NTHREADS;
                const int arr = f >> 11, rem = f & 2047;
                const int n = rem >> 3, c = rem & 7;
                const uint32_t dst = sb + (arr ? dbl : dbh) + n * (B_STRIDE * 2) + c * 16;
                const __nv_bfloat16* src = (arr ? g_Rl : g_Rh) + (size_t)n * DIMX + nk * 64 + c * 8;
                cp16(dst, src);
            }
            cp_commit();
        }
    }

    // ---- fused epilogue ----
    const __nv_bfloat16* sAh = reinterpret_cast<const __nv_bfloat16*>(smem + SM_AH);
    const __nv_bfloat16* sAl = reinterpret_cast<const __nv_bfloat16*>(smem + SM_AL);
    float q[2] = {0, 0};
    float nn[2] = {0, 0};
    #pragma unroll
    for (int ni = 0; ni < 4; ni++) {
        const int j0 = n_base + ni * 8 + (lane & 3) * 2;
        const int r0 = mg * 16 + (lane >> 2);
        #pragma unroll
        for (int e = 0; e < 4; e++) {
            const int r = r0 + (e >> 1) * 8;
            const int j = j0 + (e & 1);
            const float xf = __bfloat162float(sAh[r * A_STRIDE + j]) +
                             __bfloat162float(sAl[r * A_STRIDE + j]);
            const int s = e >> 1;
            q[s] = fmaf(acc[ni][e], xf, q[s]);
            nn[s] = fmaf(xf, xf, nn[s]);
        }
    }
    #pragma unroll
    for (int off = 1; off <= 2; off <<= 1) {
        #pragma unroll
        for (int s = 0; s < 2; s++) {
            q[s] += __shfl_xor_sync(0xffffffffu, q[s], off);
            nn[s] += __shfl_xor_sync(0xffffffffu, nn[s], off);
        }
    }
    float* qp = reinterpret_cast<float*>(smem + SM_QP);
    float* np = reinterpret_cast<float*>(smem + SM_NP);
    if ((lane & 3) == 0) {
        #pragma unroll
        for (int s = 0; s < 2; s++) {
            const int rloc = (lane >> 2) + s * 8;     // 0..15 within M half
            qp[wid * 16 + rloc] = q[s];
            np[wid * 16 + rloc] = nn[s];
        }
    }
    __syncthreads();

    if (t < TILE_M) {
        const int mgf = t >> 4, rloc = t & 15;
        float qq = 0.0f, ns = 0.0f;
        #pragma unroll
        for (int w = 0; w < 8; w++) {
            qq += qp[(mgf * 8 + w) * 16 + rloc];
            ns += np[(mgf * 8 + w) * 16 + rloc];
        }
        out[b0 + t] = qq * ns;
    }
}

extern "C" void kernel_launch(void* const* d_in, const int* in_sizes, int n_in,
                              void* d_out, int out_size) {
    const float* X   = (const float*)d_in[0];
    const float* rho = (const float*)d_in[1];
    float* out = (float*)d_out;

    const int NR4 = DIMX * DIMX / 4;
    cvt_rho<<<(NR4 + 255) / 256, 256>>>(rho);

    cudaFuncSetAttribute(qmd_mma, cudaFuncAttributeMaxDynamicSharedMemorySize, SMEM_TOTAL);
    qmd_mma<<<out_size / TILE_M, NTHREADS, SMEM_TOTAL>>>(X, out);
}